// round 1
// baseline (speedup 1.0000x reference)
#include <cuda_runtime.h>
#include <cstdint>

// Problem constants (fixed by the dataset)
#define DIN   4096
#define DOUT  4096
#define MROWS 8192   // B*S = 4*2048
#define RANK  16

// Effective weight scratch: W_eff[n][k] = scale*Q[n][k] + (A@B)[k][n], TF32-rounded.
// __device__ global (allocation-free per harness rules). 64 MB.
__device__ float g_Weff[(size_t)DOUT * DIN];

// ---------------------------------------------------------------------------
// Prep: fold dequant + LoRA into W_eff, round to TF32 (rna) so the GEMM's
// B-operand needs no further conversion.
// ---------------------------------------------------------------------------
__global__ void prep_weff_kernel(const int*   __restrict__ qw,
                                 const float* __restrict__ scales,
                                 const float* __restrict__ lA,   // [DIN][RANK]
                                 const float* __restrict__ lB) { // [RANK][DOUT]
    size_t idx = (size_t)blockIdx.x * blockDim.x + threadIdx.x;
    if (idx >= (size_t)DOUT * DIN) return;
    int n = (int)(idx / DIN);
    int k = (int)(idx % DIN);
    float w = (float)qw[idx] * scales[0];
    float acc = 0.f;
#pragma unroll
    for (int r = 0; r < RANK; r++)
        acc += lA[(size_t)k * RANK + r] * lB[(size_t)r * DOUT + n];
    w += acc;  // SCALING = alpha/rank = 1.0
    uint32_t u;
    asm("cvt.rna.tf32.f32 %0, %1;" : "=r"(u) : "f"(w));
    g_Weff[idx] = __uint_as_float(u);
}

// ---------------------------------------------------------------------------
// Main GEMM: out[m][n] = sum_k x[m][k] * W_eff[n][k] + bias[n]
// TF32 mma.sync m16n8k8, fp32 accumulate.
// CTA tile 128x128, BK=32, 8 warps (2x4), warp tile 64x32.
// ---------------------------------------------------------------------------
#define BM 128
#define BN 128
#define BK 32

__global__ __launch_bounds__(256, 1)
void qlora_gemm_kernel(const float* __restrict__ x,
                       const float* __restrict__ bias,
                       float*       __restrict__ out) {
    __shared__ __align__(16) float sA[BM][BK + 4];
    __shared__ __align__(16) float sB[BN][BK + 4];

    const int bm   = blockIdx.y * BM;
    const int bn   = blockIdx.x * BN;
    const int tid  = threadIdx.x;
    const int warp = tid >> 5;
    const int lane = tid & 31;
    const int wm   = (warp >> 2) * 64;   // warp row offset within CTA tile
    const int wn   = (warp & 3)  * 32;   // warp col offset within CTA tile
    const int grp  = lane >> 2;          // 0..7
    const int tig  = lane & 3;           // 0..3

    float c[4][4][4];
#pragma unroll
    for (int i = 0; i < 4; i++)
#pragma unroll
        for (int j = 0; j < 4; j++)
#pragma unroll
            for (int q = 0; q < 4; q++) c[i][j][q] = 0.f;

    for (int k0 = 0; k0 < DIN; k0 += BK) {
        // Cooperative loads: 128x32 floats each for A and B; 4 float4 per thread each.
#pragma unroll
        for (int i = 0; i < 4; i++) {
            int id = tid + i * 256;
            int r  = id >> 3;            // 0..127
            int c4 = (id & 7) << 2;      // 0,4,...,28
            float4 va = *reinterpret_cast<const float4*>(
                &x[(size_t)(bm + r) * DIN + k0 + c4]);
            *reinterpret_cast<float4*>(&sA[r][c4]) = va;
            float4 vb = *reinterpret_cast<const float4*>(
                &g_Weff[(size_t)(bn + r) * DIN + k0 + c4]);
            *reinterpret_cast<float4*>(&sB[r][c4]) = vb;
        }
        __syncthreads();

#pragma unroll
        for (int kk = 0; kk < BK; kk += 8) {
            uint32_t a[4][4];
            uint32_t b[4][2];
#pragma unroll
            for (int mt = 0; mt < 4; mt++) {
                int row0 = wm + mt * 16;
                float f0 = sA[row0 + grp    ][kk + tig    ];
                float f1 = sA[row0 + grp + 8][kk + tig    ];
                float f2 = sA[row0 + grp    ][kk + tig + 4];
                float f3 = sA[row0 + grp + 8][kk + tig + 4];
                // x must be TF32-rounded with round-to-nearest (unbiased).
                asm("cvt.rna.tf32.f32 %0, %1;" : "=r"(a[mt][0]) : "f"(f0));
                asm("cvt.rna.tf32.f32 %0, %1;" : "=r"(a[mt][1]) : "f"(f1));
                asm("cvt.rna.tf32.f32 %0, %1;" : "=r"(a[mt][2]) : "f"(f2));
                asm("cvt.rna.tf32.f32 %0, %1;" : "=r"(a[mt][3]) : "f"(f3));
            }
#pragma unroll
            for (int nt = 0; nt < 4; nt++) {
                int col0 = wn + nt * 8;
                // W_eff already TF32-rounded in prep — no cvt needed.
                b[nt][0] = __float_as_uint(sB[col0 + grp][kk + tig    ]);
                b[nt][1] = __float_as_uint(sB[col0 + grp][kk + tig + 4]);
            }
#pragma unroll
            for (int mt = 0; mt < 4; mt++)
#pragma unroll
                for (int nt = 0; nt < 4; nt++) {
                    asm volatile(
                        "mma.sync.aligned.m16n8k8.row.col.f32.tf32.tf32.f32 "
                        "{%0,%1,%2,%3}, {%4,%5,%6,%7}, {%8,%9}, {%0,%1,%2,%3};\n"
                        : "+f"(c[mt][nt][0]), "+f"(c[mt][nt][1]),
                          "+f"(c[mt][nt][2]), "+f"(c[mt][nt][3])
                        : "r"(a[mt][0]), "r"(a[mt][1]), "r"(a[mt][2]), "r"(a[mt][3]),
                          "r"(b[nt][0]), "r"(b[nt][1]));
                }
        }
        __syncthreads();
    }

    // Epilogue: + bias, fp32 out, float2 stores.
#pragma unroll
    for (int nt = 0; nt < 4; nt++) {
        int col = bn + wn + nt * 8 + tig * 2;
        float b0 = bias[col];
        float b1 = bias[col + 1];
#pragma unroll
        for (int mt = 0; mt < 4; mt++) {
            int row = bm + wm + mt * 16 + grp;
            float2 v0 = make_float2(c[mt][nt][0] + b0, c[mt][nt][1] + b1);
            float2 v1 = make_float2(c[mt][nt][2] + b0, c[mt][nt][3] + b1);
            *reinterpret_cast<float2*>(&out[(size_t)row       * DOUT + col]) = v0;
            *reinterpret_cast<float2*>(&out[(size_t)(row + 8) * DOUT + col]) = v1;
        }
    }
}

// ---------------------------------------------------------------------------
// Launch: prep (fold dequant+LoRA) then one dense GEMM. Graph-capturable:
// kernel launches only, no sync, no allocation.
// ---------------------------------------------------------------------------
extern "C" void kernel_launch(void* const* d_in, const int* in_sizes, int n_in,
                              void* d_out, int out_size) {
    const float* x      = (const float*)d_in[0];
    const int*   qw     = (const int*)  d_in[1];
    const float* scales = (const float*)d_in[2];
    const float* bias   = (const float*)d_in[3];
    const float* lA     = (const float*)d_in[4];
    const float* lB     = (const float*)d_in[5];
    float*       out    = (float*)d_out;

    {
        size_t total = (size_t)DOUT * DIN;
        int threads = 256;
        int blocks  = (int)((total + threads - 1) / threads);
        prep_weff_kernel<<<blocks, threads>>>(qw, scales, lA, lB);
    }
    {
        dim3 grid(DOUT / BN, MROWS / BM);
        qlora_gemm_kernel<<<grid, 256>>>(x, bias, out);
    }
}

// round 7
// speedup vs baseline: 2.3013x; 2.3013x over previous
#include <cuda_runtime.h>
#include <cuda_fp16.h>
#include <cstdint>

#define DIN   4096
#define DOUT  4096
#define MROWS 8192
#define RANK  16

#define BM 128
#define BN 256
#define BK 32
#define STAGES 4
#define NCHUNK (DIN / BK)            // 128

// 80-byte row stride (40 halves): conflict-free for ldmatrix and cp.async.
#define ROWB 80
#define A_BYTES (BM * ROWB)          // 10240
#define B_BYTES (BN * ROWB)          // 20480
#define STAGE_BYTES (A_BYTES + B_BYTES)  // 30720
#define SMEM_DYN (STAGES * STAGE_BYTES + 2048)  // ~125 KB

// fp16 operand scratch (allocation-free __device__ globals)
__device__ __half g_Xh[(size_t)MROWS * DIN];   // 64 MB
__device__ __half g_Wh[(size_t)DOUT * DIN];    // 32 MB  W_eff[n][k]

// ---------------------------------------------------------------------------
// Prep 1: W_eff[n][k] = scale*Q[n][k] + (A@B)[k][n], rounded to fp16 (rn).
// ---------------------------------------------------------------------------
__global__ void prep_w_kernel(const int*   __restrict__ qw,
                              const float* __restrict__ scales,
                              const float* __restrict__ lA,   // [DIN][RANK]
                              const float* __restrict__ lB) { // [RANK][DOUT]
    size_t idx = (size_t)blockIdx.x * blockDim.x + threadIdx.x;
    if (idx >= (size_t)DOUT * DIN) return;
    int n = (int)(idx / DIN);
    int k = (int)(idx % DIN);
    float w = (float)qw[idx] * scales[0];
    float acc = 0.f;
#pragma unroll
    for (int r = 0; r < RANK; r++)
        acc += lA[(size_t)k * RANK + r] * lB[(size_t)r * DOUT + n];
    g_Wh[idx] = __float2half_rn(w + acc);
}

// ---------------------------------------------------------------------------
// Prep 2: x fp32 -> fp16 (rn). 8 elements per thread, vectorized.
// ---------------------------------------------------------------------------
__global__ void prep_x_kernel(const float* __restrict__ x) {
    size_t t = (size_t)blockIdx.x * blockDim.x + threadIdx.x;
    size_t base = t * 8;
    if (base >= (size_t)MROWS * DIN) return;
    float4 v0 = *reinterpret_cast<const float4*>(x + base);
    float4 v1 = *reinterpret_cast<const float4*>(x + base + 4);
    __half2 h[4];
    h[0] = __floats2half2_rn(v0.x, v0.y);
    h[1] = __floats2half2_rn(v0.z, v0.w);
    h[2] = __floats2half2_rn(v1.x, v1.y);
    h[3] = __floats2half2_rn(v1.z, v1.w);
    *reinterpret_cast<uint4*>(&g_Xh[base]) = *reinterpret_cast<uint4*>(h);
}

// ---------------------------------------------------------------------------
__device__ __forceinline__ uint32_t smem_u32(const void* p) {
    uint32_t a;
    asm("{ .reg .u64 t; cvta.to.shared.u64 t, %1; cvt.u32.u64 %0, t; }" : "=r"(a) : "l"(p));
    return a;
}
__device__ __forceinline__ void cp16(uint32_t dst, const void* src) {
    asm volatile("cp.async.cg.shared.global [%0], [%1], 16;" :: "r"(dst), "l"(src));
}
__device__ __forceinline__ void ldsm4(uint32_t& r0, uint32_t& r1, uint32_t& r2,
                                      uint32_t& r3, uint32_t addr) {
    asm volatile("ldmatrix.sync.aligned.m8n8.x4.shared.b16 {%0,%1,%2,%3}, [%4];"
                 : "=r"(r0), "=r"(r1), "=r"(r2), "=r"(r3) : "r"(addr));
}
__device__ __forceinline__ void mma16816(float* c, const uint32_t* a,
                                         const uint32_t* b) {
    asm volatile(
        "mma.sync.aligned.m16n8k16.row.col.f32.f16.f16.f32 "
        "{%0,%1,%2,%3}, {%4,%5,%6,%7}, {%8,%9}, {%0,%1,%2,%3};\n"
        : "+f"(c[0]), "+f"(c[1]), "+f"(c[2]), "+f"(c[3])
        : "r"(a[0]), "r"(a[1]), "r"(a[2]), "r"(a[3]), "r"(b[0]), "r"(b[1]));
}

// ---------------------------------------------------------------------------
// GEMM: out[m][n] = sum_k Xh[m][k]*Wh[n][k] + bias[n]
// CTA 128x256, 8 warps (2x4), warp tile 64x64, BK=32, 4-stage cp.async.
// ---------------------------------------------------------------------------
__global__ __launch_bounds__(256)
void qlora_hmma_kernel(const float* __restrict__ bias,
                       float*       __restrict__ out) {
    extern __shared__ char smem_raw[];
    uint32_t sbase = smem_u32(smem_raw);
    float* sbias = (float*)(smem_raw + STAGES * STAGE_BYTES);

    const int tid  = threadIdx.x;
    const int warp = tid >> 5;
    const int lane = tid & 31;
    const int bm = blockIdx.y * BM;
    const int bn = blockIdx.x * BN;
    const int wm = (warp >> 2) * 64;       // 0 or 64
    const int wn = (warp & 3) * 64;        // 0..192

    // bias tile
    sbias[tid] = bias[bn + tid];

    // ldmatrix per-lane offsets (within a tile slot, before row-base)
    const uint32_t a_loff = (uint32_t)((lane & 15) * ROWB + (lane >> 4) * 16);
    const uint32_t b_loff = (uint32_t)((((lane >> 4) << 3) + (lane & 7)) * ROWB
                                       + ((lane >> 3) & 1) * 16);

    float c[4][8][4];
#pragma unroll
    for (int i = 0; i < 4; i++)
#pragma unroll
        for (int j = 0; j < 8; j++)
#pragma unroll
            for (int q = 0; q < 4; q++) c[i][j][q] = 0.f;

    // ---- cooperative load of one chunk into a stage slot ----
    auto load_chunk = [&](int chunk, int slot) {
        const int k0 = chunk * BK;
        uint32_t abase = sbase + slot * STAGE_BYTES;
        uint32_t bbase = abase + A_BYTES;
#pragma unroll
        for (int j = 0; j < 2; j++) {               // A: 512 chunks of 16B
            int id = tid + j * 256;
            int row = id >> 2, cc = id & 3;
            cp16(abase + row * ROWB + cc * 16,
                 &g_Xh[(size_t)(bm + row) * DIN + k0 + cc * 8]);
        }
#pragma unroll
        for (int j = 0; j < 4; j++) {               // B: 1024 chunks of 16B
            int id = tid + j * 256;
            int row = id >> 2, cc = id & 3;
            cp16(bbase + row * ROWB + cc * 16,
                 &g_Wh[(size_t)(bn + row) * DIN + k0 + cc * 8]);
        }
    };

    // ---- prologue: stages 0..2 ----
#pragma unroll
    for (int s = 0; s < STAGES - 1; s++) {
        load_chunk(s, s);
        asm volatile("cp.async.commit_group;" ::: "memory");
    }

    // ---- mainloop ----
    for (int i = 0; i < NCHUNK; i++) {
        asm volatile("cp.async.wait_group %0;" :: "n"(STAGES - 2) : "memory");
        __syncthreads();

        // issue loads for chunk i+3 (into slot freed by chunk i-1)
        if (i + STAGES - 1 < NCHUNK)
            load_chunk(i + STAGES - 1, (i + STAGES - 1) % STAGES);
        asm volatile("cp.async.commit_group;" ::: "memory");

        // compute chunk i
        const int slot = i % STAGES;
        uint32_t abase = sbase + slot * STAGE_BYTES + (uint32_t)wm * ROWB + a_loff;
        uint32_t bbase = sbase + slot * STAGE_BYTES + A_BYTES + (uint32_t)wn * ROWB + b_loff;
#pragma unroll
        for (int s = 0; s < 2; s++) {               // two k16 steps per BK=32
            uint32_t a[4][4], b[4][4];
#pragma unroll
            for (int mt = 0; mt < 4; mt++)
                ldsm4(a[mt][0], a[mt][1], a[mt][2], a[mt][3],
                      abase + (uint32_t)(mt * 16 * ROWB + s * 32));
#pragma unroll
            for (int g = 0; g < 4; g++)
                ldsm4(b[g][0], b[g][1], b[g][2], b[g][3],
                      bbase + (uint32_t)(g * 16 * ROWB + s * 32));
#pragma unroll
            for (int mt = 0; mt < 4; mt++)
#pragma unroll
                for (int g = 0; g < 4; g++) {
                    mma16816(c[mt][2 * g],     a[mt], &b[g][0]);
                    mma16816(c[mt][2 * g + 1], a[mt], &b[g][2]);
                }
        }
        __syncthreads();
    }

    // ---- epilogue: + bias, fp32 stores ----
    const int qrow = lane >> 2;           // 0..7
    const int qcol = (lane & 3) * 2;      // 0,2,4,6
#pragma unroll
    for (int mt = 0; mt < 4; mt++) {
        int r0 = bm + wm + mt * 16 + qrow;
#pragma unroll
        for (int g = 0; g < 4; g++) {
#pragma unroll
            for (int h = 0; h < 2; h++) {
                int col = bn + wn + g * 16 + h * 8 + qcol;
                float b0 = sbias[col - bn];
                float b1 = sbias[col - bn + 1];
                float* cc = c[mt][2 * g + h];
                *reinterpret_cast<float2*>(&out[(size_t)r0 * DOUT + col]) =
                    make_float2(cc[0] + b0, cc[1] + b1);
                *reinterpret_cast<float2*>(&out[(size_t)(r0 + 8) * DOUT + col]) =
                    make_float2(cc[2] + b0, cc[3] + b1);
            }
        }
    }
}

// ---------------------------------------------------------------------------
extern "C" void kernel_launch(void* const* d_in, const int* in_sizes, int n_in,
                              void* d_out, int out_size) {
    const float* x      = (const float*)d_in[0];
    const int*   qw     = (const int*)  d_in[1];
    const float* scales = (const float*)d_in[2];
    const float* bias   = (const float*)d_in[3];
    const float* lA     = (const float*)d_in[4];
    const float* lB     = (const float*)d_in[5];
    float*       out    = (float*)d_out;

    {
        size_t total = (size_t)DOUT * DIN;
        prep_w_kernel<<<(int)((total + 255) / 256), 256>>>(qw, scales, lA, lB);
    }
    {
        size_t total = (size_t)MROWS * DIN / 8;
        prep_x_kernel<<<(int)((total + 255) / 256), 256>>>(x);
    }
    {
        cudaFuncSetAttribute(qlora_hmma_kernel,
                             cudaFuncAttributeMaxDynamicSharedMemorySize, SMEM_DYN);
        dim3 grid(DOUT / BN, MROWS / BM);
        qlora_hmma_kernel<<<grid, 256, SMEM_DYN>>>(bias, out);
    }
}

// round 8
// speedup vs baseline: 3.2672x; 1.4197x over previous
#include <cuda_runtime.h>
#include <cuda_fp16.h>
#include <cstdint>

#define DIN   4096
#define DOUT  4096
#define MROWS 8192
#define RANK  16

#define BM 128
#define BN 256
#define BK 32
#define STAGES 5
#define NCHUNK (DIN / BK)            // 128

// 80-byte row stride (40 halves): conflict-free for ldmatrix and cp.async.
#define ROWB 80
#define A_BYTES (BM * ROWB)          // 10240
#define B_BYTES (BN * ROWB)          // 20480
#define STAGE_BYTES (A_BYTES + B_BYTES)  // 30720
#define SMEM_DYN (STAGES * STAGE_BYTES + 2048)  // ~155 KB

// fp16 operand scratch (allocation-free __device__ globals)
__device__ __half g_Xh[(size_t)MROWS * DIN];   // 64 MB
__device__ __half g_Wh[(size_t)DOUT * DIN];    // 32 MB  W_eff[n][k]

// ---------------------------------------------------------------------------
// Prep 1: W_eff[n][k] = scale*Q[n][k] + (A@B)[k][n], fp16(rn).
// Register-blocked: thread owns lA rows k0,k0+1 (32 regs), loops 8 n-values.
// lB loads are warp-uniform broadcasts; qw int2; half2 stores.
// ---------------------------------------------------------------------------
__global__ __launch_bounds__(256)
void prep_w_kernel(const int*   __restrict__ qw,
                   const float* __restrict__ scales,
                   const float* __restrict__ lA,   // [DIN][RANK]
                   const float* __restrict__ lB) { // [RANK][DOUT]
    const int lane = threadIdx.x & 31;
    const int w    = threadIdx.x >> 5;
    const int k0   = blockIdx.x * 64 + lane * 2;
    const int nb   = blockIdx.y * 64 + w * 8;

    float a[32];  // a[0..15] = lA[k0][:], a[16..31] = lA[k0+1][:]
    const float4* pa = reinterpret_cast<const float4*>(&lA[(size_t)k0 * RANK]);
#pragma unroll
    for (int q = 0; q < 8; q++)
        reinterpret_cast<float4*>(a)[q] = pa[q];

    const float s = scales[0];
#pragma unroll
    for (int j = 0; j < 8; j++) {
        const int n = nb + j;
        int2 q2 = *reinterpret_cast<const int2*>(&qw[(size_t)n * DIN + k0]);
        float acc0 = (float)q2.x * s;
        float acc1 = (float)q2.y * s;
#pragma unroll
        for (int r = 0; r < RANK; r++) {
            float b = __ldg(&lB[(size_t)r * DOUT + n]);
            acc0 += a[r]      * b;
            acc1 += a[16 + r] * b;
        }
        *reinterpret_cast<__half2*>(&g_Wh[(size_t)n * DIN + k0]) =
            __floats2half2_rn(acc0, acc1);
    }
}

// ---------------------------------------------------------------------------
// Prep 2: x fp32 -> fp16 (rn). 8 elements per thread, vectorized.
// ---------------------------------------------------------------------------
__global__ void prep_x_kernel(const float* __restrict__ x) {
    size_t t = (size_t)blockIdx.x * blockDim.x + threadIdx.x;
    size_t base = t * 8;
    if (base >= (size_t)MROWS * DIN) return;
    float4 v0 = *reinterpret_cast<const float4*>(x + base);
    float4 v1 = *reinterpret_cast<const float4*>(x + base + 4);
    __half2 h[4];
    h[0] = __floats2half2_rn(v0.x, v0.y);
    h[1] = __floats2half2_rn(v0.z, v0.w);
    h[2] = __floats2half2_rn(v1.x, v1.y);
    h[3] = __floats2half2_rn(v1.z, v1.w);
    *reinterpret_cast<uint4*>(&g_Xh[base]) = *reinterpret_cast<uint4*>(h);
}

// ---------------------------------------------------------------------------
__device__ __forceinline__ uint32_t smem_u32(const void* p) {
    uint32_t a;
    asm("{ .reg .u64 t; cvta.to.shared.u64 t, %1; cvt.u32.u64 %0, t; }" : "=r"(a) : "l"(p));
    return a;
}
__device__ __forceinline__ void cp16(uint32_t dst, const void* src) {
    asm volatile("cp.async.cg.shared.global [%0], [%1], 16;" :: "r"(dst), "l"(src));
}
__device__ __forceinline__ void ldsm4(uint32_t& r0, uint32_t& r1, uint32_t& r2,
                                      uint32_t& r3, uint32_t addr) {
    asm volatile("ldmatrix.sync.aligned.m8n8.x4.shared.b16 {%0,%1,%2,%3}, [%4];"
                 : "=r"(r0), "=r"(r1), "=r"(r2), "=r"(r3) : "r"(addr));
}
__device__ __forceinline__ void mma16816(float* c, const uint32_t* a,
                                         const uint32_t* b) {
    asm volatile(
        "mma.sync.aligned.m16n8k16.row.col.f32.f16.f16.f32 "
        "{%0,%1,%2,%3}, {%4,%5,%6,%7}, {%8,%9}, {%0,%1,%2,%3};\n"
        : "+f"(c[0]), "+f"(c[1]), "+f"(c[2]), "+f"(c[3])
        : "r"(a[0]), "r"(a[1]), "r"(a[2]), "r"(a[3]), "r"(b[0]), "r"(b[1]));
}

// ---------------------------------------------------------------------------
// GEMM: out[m][n] = sum_k Xh[m][k]*Wh[n][k] + bias[n]
// CTA 128x256, 8 warps (2x4), warp tile 64x64, BK=32, 5-stage cp.async,
// single barrier per mainloop iteration.
// ---------------------------------------------------------------------------
__global__ __launch_bounds__(256)
void qlora_hmma_kernel(const float* __restrict__ bias,
                       float*       __restrict__ out) {
    extern __shared__ char smem_raw[];
    uint32_t sbase = smem_u32(smem_raw);
    float* sbias = (float*)(smem_raw + STAGES * STAGE_BYTES);

    const int tid  = threadIdx.x;
    const int warp = tid >> 5;
    const int lane = tid & 31;
    const int bm = blockIdx.y * BM;
    const int bn = blockIdx.x * BN;
    const int wm = (warp >> 2) * 64;       // 0 or 64
    const int wn = (warp & 3) * 64;        // 0..192

    // bias tile (consumed after many barriers — safe)
    sbias[tid] = bias[bn + tid];

    // ldmatrix per-lane offsets (within a tile slot, before row-base)
    const uint32_t a_loff = (uint32_t)((lane & 15) * ROWB + (lane >> 4) * 16);
    const uint32_t b_loff = (uint32_t)((((lane >> 4) << 3) + (lane & 7)) * ROWB
                                       + ((lane >> 3) & 1) * 16);

    float c[4][8][4];
#pragma unroll
    for (int i = 0; i < 4; i++)
#pragma unroll
        for (int j = 0; j < 8; j++)
#pragma unroll
            for (int q = 0; q < 4; q++) c[i][j][q] = 0.f;

    auto load_chunk = [&](int chunk, int slot) {
        const int k0 = chunk * BK;
        uint32_t abase = sbase + slot * STAGE_BYTES;
        uint32_t bbase = abase + A_BYTES;
#pragma unroll
        for (int j = 0; j < 2; j++) {               // A: 512 chunks of 16B
            int id = tid + j * 256;
            int row = id >> 2, cc = id & 3;
            cp16(abase + row * ROWB + cc * 16,
                 &g_Xh[(size_t)(bm + row) * DIN + k0 + cc * 8]);
        }
#pragma unroll
        for (int j = 0; j < 4; j++) {               // B: 1024 chunks of 16B
            int id = tid + j * 256;
            int row = id >> 2, cc = id & 3;
            cp16(bbase + row * ROWB + cc * 16,
                 &g_Wh[(size_t)(bn + row) * DIN + k0 + cc * 8]);
        }
    };

    // ---- prologue: stages 0..STAGES-2 ----
#pragma unroll
    for (int s = 0; s < STAGES - 1; s++) {
        load_chunk(s, s);
        asm volatile("cp.async.commit_group;" ::: "memory");
    }

    // ---- mainloop: one barrier per iteration ----
    for (int i = 0; i < NCHUNK; i++) {
        asm volatile("cp.async.wait_group %0;" :: "n"(STAGES - 2) : "memory");
        __syncthreads();

        // loads for chunk i+STAGES-1 go into the slot chunk i-1 just vacated
        if (i + STAGES - 1 < NCHUNK)
            load_chunk(i + STAGES - 1, (i + STAGES - 1) % STAGES);
        asm volatile("cp.async.commit_group;" ::: "memory");

        const int slot = i % STAGES;
        uint32_t abase = sbase + slot * STAGE_BYTES + (uint32_t)wm * ROWB + a_loff;
        uint32_t bbase = sbase + slot * STAGE_BYTES + A_BYTES + (uint32_t)wn * ROWB + b_loff;
#pragma unroll
        for (int s = 0; s < 2; s++) {               // two k16 steps per BK=32
            uint32_t a[4][4], b[4][4];
#pragma unroll
            for (int mt = 0; mt < 4; mt++)
                ldsm4(a[mt][0], a[mt][1], a[mt][2], a[mt][3],
                      abase + (uint32_t)(mt * 16 * ROWB + s * 32));
#pragma unroll
            for (int g = 0; g < 4; g++)
                ldsm4(b[g][0], b[g][1], b[g][2], b[g][3],
                      bbase + (uint32_t)(g * 16 * ROWB + s * 32));
#pragma unroll
            for (int mt = 0; mt < 4; mt++)
#pragma unroll
                for (int g = 0; g < 4; g++) {
                    mma16816(c[mt][2 * g],     a[mt], &b[g][0]);
                    mma16816(c[mt][2 * g + 1], a[mt], &b[g][2]);
                }
        }
        // no trailing barrier: next iteration's top barrier protects slot reuse
    }

    // ---- epilogue: + bias, fp32 stores ----
    const int qrow = lane >> 2;           // 0..7
    const int qcol = (lane & 3) * 2;      // 0,2,4,6
#pragma unroll
    for (int mt = 0; mt < 4; mt++) {
        int r0 = bm + wm + mt * 16 + qrow;
#pragma unroll
        for (int g = 0; g < 4; g++) {
#pragma unroll
            for (int h = 0; h < 2; h++) {
                int col = bn + wn + g * 16 + h * 8 + qcol;
                float b0 = sbias[col - bn];
                float b1 = sbias[col - bn + 1];
                float* cc = c[mt][2 * g + h];
                *reinterpret_cast<float2*>(&out[(size_t)r0 * DOUT + col]) =
                    make_float2(cc[0] + b0, cc[1] + b1);
                *reinterpret_cast<float2*>(&out[(size_t)(r0 + 8) * DOUT + col]) =
                    make_float2(cc[2] + b0, cc[3] + b1);
            }
        }
    }
}

// ---------------------------------------------------------------------------
extern "C" void kernel_launch(void* const* d_in, const int* in_sizes, int n_in,
                              void* d_out, int out_size) {
    const float* x      = (const float*)d_in[0];
    const int*   qw     = (const int*)  d_in[1];
    const float* scales = (const float*)d_in[2];
    const float* bias   = (const float*)d_in[3];
    const float* lA     = (const float*)d_in[4];
    const float* lB     = (const float*)d_in[5];
    float*       out    = (float*)d_out;

    {
        dim3 grid(DIN / 64, DOUT / 64);
        prep_w_kernel<<<grid, 256>>>(qw, scales, lA, lB);
    }
    {
        size_t total = (size_t)MROWS * DIN / 8;
        prep_x_kernel<<<(int)((total + 255) / 256), 256>>>(x);
    }
    {
        cudaFuncSetAttribute(qlora_hmma_kernel,
                             cudaFuncAttributeMaxDynamicSharedMemorySize, SMEM_DYN);
        dim3 grid(DOUT / BN, MROWS / BM);
        qlora_hmma_kernel<<<grid, 256, SMEM_DYN>>>(bias, out);
    }
}

// round 9
// speedup vs baseline: 3.3047x; 1.0115x over previous
#include <cuda_runtime.h>
#include <cuda_fp16.h>
#include <cstdint>

#define DIN   4096
#define DOUT  4096
#define MROWS 8192
#define RANK  16

#define BM 128
#define BN 256
#define BK 32
#define STAGES 5
#define NCHUNK (DIN / BK)            // 128

// 80-byte row stride (40 halves): conflict-free ldmatrix.
#define ROWB 80
#define A_BYTES (BM * ROWB)          // 10240
#define B_BYTES (BN * ROWB)          // 20480
#define STAGE_BYTES (A_BYTES + B_BYTES)  // 30720
#define SMEM_DYN (STAGES * STAGE_BYTES + 2048)  // ~155 KB

// fp16 operand scratch (allocation-free __device__ globals)
__device__ __half g_Xh[(size_t)MROWS * DIN];   // 64 MB
__device__ __half g_Wh[(size_t)DOUT * DIN];    // 32 MB  W_eff[n][k]

// ---------------------------------------------------------------------------
// Prep 1: W_eff[n][k] = scale*Q[n][k] + (A@B)[k][n], fp16(rn).
// lA rows in registers; lB staged through smem (broadcast reads).
// ---------------------------------------------------------------------------
__global__ __launch_bounds__(256)
void prep_w_kernel(const int*   __restrict__ qw,
                   const float* __restrict__ scales,
                   const float* __restrict__ lA,   // [DIN][RANK]
                   const float* __restrict__ lB) { // [RANK][DOUT]
    __shared__ float sB[RANK * 64];                // lB[r][nb0..nb0+64)
    const int tid  = threadIdx.x;
    const int lane = tid & 31;
    const int w    = tid >> 5;
    const int k0   = blockIdx.x * 64 + lane * 2;
    const int nb0  = blockIdx.y * 64;

    // stage lB slice: 1024 floats, coalesced (64 consecutive n per row r)
#pragma unroll
    for (int j = 0; j < 4; j++) {
        int idx = tid + j * 256;
        int r = idx >> 6, n = idx & 63;
        sB[idx] = lB[(size_t)r * DOUT + nb0 + n];
    }

    float a[32];  // a[0..15] = lA[k0][:], a[16..31] = lA[k0+1][:]
    const float4* pa = reinterpret_cast<const float4*>(&lA[(size_t)k0 * RANK]);
#pragma unroll
    for (int q = 0; q < 8; q++)
        reinterpret_cast<float4*>(a)[q] = pa[q];

    __syncthreads();

    const float s = scales[0];
#pragma unroll
    for (int j = 0; j < 8; j++) {
        const int nl = w * 8 + j;                  // 0..63 within block
        const int n  = nb0 + nl;
        int2 q2 = *reinterpret_cast<const int2*>(&qw[(size_t)n * DIN + k0]);
        float acc0 = (float)q2.x * s;
        float acc1 = (float)q2.y * s;
#pragma unroll
        for (int r = 0; r < RANK; r++) {
            float b = sB[r * 64 + nl];             // warp-uniform broadcast
            acc0 += a[r]      * b;
            acc1 += a[16 + r] * b;
        }
        *reinterpret_cast<__half2*>(&g_Wh[(size_t)n * DIN + k0]) =
            __floats2half2_rn(acc0, acc1);
    }
}

// ---------------------------------------------------------------------------
// Prep 2: x fp32 -> fp16 (rn). 8 elements per thread, vectorized.
// ---------------------------------------------------------------------------
__global__ void prep_x_kernel(const float* __restrict__ x) {
    size_t t = (size_t)blockIdx.x * blockDim.x + threadIdx.x;
    size_t base = t * 8;
    if (base >= (size_t)MROWS * DIN) return;
    float4 v0 = *reinterpret_cast<const float4*>(x + base);
    float4 v1 = *reinterpret_cast<const float4*>(x + base + 4);
    __half2 h[4];
    h[0] = __floats2half2_rn(v0.x, v0.y);
    h[1] = __floats2half2_rn(v0.z, v0.w);
    h[2] = __floats2half2_rn(v1.x, v1.y);
    h[3] = __floats2half2_rn(v1.z, v1.w);
    *reinterpret_cast<uint4*>(&g_Xh[base]) = *reinterpret_cast<uint4*>(h);
}

// ---------------------------------------------------------------------------
__device__ __forceinline__ uint32_t smem_u32(const void* p) {
    uint32_t a;
    asm("{ .reg .u64 t; cvta.to.shared.u64 t, %1; cvt.u32.u64 %0, t; }" : "=r"(a) : "l"(p));
    return a;
}
__device__ __forceinline__ void cp16(uint32_t dst, const void* src) {
    asm volatile("cp.async.cg.shared.global [%0], [%1], 16;" :: "r"(dst), "l"(src));
}
__device__ __forceinline__ void ldsm4(uint32_t& r0, uint32_t& r1, uint32_t& r2,
                                      uint32_t& r3, uint32_t addr) {
    asm volatile("ldmatrix.sync.aligned.m8n8.x4.shared.b16 {%0,%1,%2,%3}, [%4];"
                 : "=r"(r0), "=r"(r1), "=r"(r2), "=r"(r3) : "r"(addr));
}
__device__ __forceinline__ void mma16816(float* c, const uint32_t* a,
                                         const uint32_t* b) {
    asm volatile(
        "mma.sync.aligned.m16n8k16.row.col.f32.f16.f16.f32 "
        "{%0,%1,%2,%3}, {%4,%5,%6,%7}, {%8,%9}, {%0,%1,%2,%3};\n"
        : "+f"(c[0]), "+f"(c[1]), "+f"(c[2]), "+f"(c[3])
        : "r"(a[0]), "r"(a[1]), "r"(a[2]), "r"(a[3]), "r"(b[0]), "r"(b[1]));
}

// ---------------------------------------------------------------------------
// GEMM: out[m][n] = sum_k Xh[m][k]*Wh[n][k] + bias[n]
// CTA 128x256, 8 warps (2x4), warp tile 64x64, BK=32, 5-stage cp.async.
// All 32 LDSM of a chunk batched before its 128 MMAs (max intra-chunk ILP).
// ---------------------------------------------------------------------------
__global__ __launch_bounds__(256)
void qlora_hmma_kernel(const float* __restrict__ bias,
                       float*       __restrict__ out) {
    extern __shared__ char smem_raw[];
    uint32_t sbase = smem_u32(smem_raw);
    float* sbias = (float*)(smem_raw + STAGES * STAGE_BYTES);

    const int tid  = threadIdx.x;
    const int warp = tid >> 5;
    const int lane = tid & 31;
    const int bm = blockIdx.y * BM;
    const int bn = blockIdx.x * BN;
    const int wm = (warp >> 2) * 64;       // 0 or 64
    const int wn = (warp & 3) * 64;        // 0..192

    sbias[tid] = bias[bn + tid];

    const uint32_t a_loff = (uint32_t)((lane & 15) * ROWB + (lane >> 4) * 16);
    const uint32_t b_loff = (uint32_t)((((lane >> 4) << 3) + (lane & 7)) * ROWB
                                       + ((lane >> 3) & 1) * 16);

    float c[4][8][4];
#pragma unroll
    for (int i = 0; i < 4; i++)
#pragma unroll
        for (int j = 0; j < 8; j++)
#pragma unroll
            for (int q = 0; q < 4; q++) c[i][j][q] = 0.f;

    auto load_chunk = [&](int chunk, int slot) {
        const int k0 = chunk * BK;
        uint32_t abase = sbase + slot * STAGE_BYTES;
        uint32_t bbase = abase + A_BYTES;
#pragma unroll
        for (int j = 0; j < 2; j++) {               // A: 512 chunks of 16B
            int id = tid + j * 256;
            int row = id >> 2, cc = id & 3;
            cp16(abase + row * ROWB + cc * 16,
                 &g_Xh[(size_t)(bm + row) * DIN + k0 + cc * 8]);
        }
#pragma unroll
        for (int j = 0; j < 4; j++) {               // B: 1024 chunks of 16B
            int id = tid + j * 256;
            int row = id >> 2, cc = id & 3;
            cp16(bbase + row * ROWB + cc * 16,
                 &g_Wh[(size_t)(bn + row) * DIN + k0 + cc * 8]);
        }
    };

    // ---- prologue ----
#pragma unroll
    for (int s = 0; s < STAGES - 1; s++) {
        load_chunk(s, s);
        asm volatile("cp.async.commit_group;" ::: "memory");
    }

    // ---- mainloop ----
    for (int i = 0; i < NCHUNK; i++) {
        asm volatile("cp.async.wait_group %0;" :: "n"(STAGES - 2) : "memory");
        __syncthreads();

        if (i + STAGES - 1 < NCHUNK)
            load_chunk(i + STAGES - 1, (i + STAGES - 1) % STAGES);
        asm volatile("cp.async.commit_group;" ::: "memory");

        const int slot = i % STAGES;
        uint32_t abase = sbase + slot * STAGE_BYTES + (uint32_t)wm * ROWB + a_loff;
        uint32_t bbase = sbase + slot * STAGE_BYTES + A_BYTES + (uint32_t)wn * ROWB + b_loff;

        // batch ALL ldmatrix for the chunk (both k16 steps), then all MMAs
        uint32_t a[2][4][4], b[2][4][4];
#pragma unroll
        for (int s = 0; s < 2; s++)
#pragma unroll
            for (int mt = 0; mt < 4; mt++)
                ldsm4(a[s][mt][0], a[s][mt][1], a[s][mt][2], a[s][mt][3],
                      abase + (uint32_t)(mt * 16 * ROWB + s * 32));
#pragma unroll
        for (int s = 0; s < 2; s++)
#pragma unroll
            for (int g = 0; g < 4; g++)
                ldsm4(b[s][g][0], b[s][g][1], b[s][g][2], b[s][g][3],
                      bbase + (uint32_t)(g * 16 * ROWB + s * 32));
#pragma unroll
        for (int s = 0; s < 2; s++)
#pragma unroll
            for (int mt = 0; mt < 4; mt++)
#pragma unroll
                for (int g = 0; g < 4; g++) {
                    mma16816(c[mt][2 * g],     a[s][mt], &b[s][g][0]);
                    mma16816(c[mt][2 * g + 1], a[s][mt], &b[s][g][2]);
                }
    }

    // ---- epilogue: + bias, fp32 stores ----
    const int qrow = lane >> 2;
    const int qcol = (lane & 3) * 2;
#pragma unroll
    for (int mt = 0; mt < 4; mt++) {
        int r0 = bm + wm + mt * 16 + qrow;
#pragma unroll
        for (int g = 0; g < 4; g++) {
#pragma unroll
            for (int h = 0; h < 2; h++) {
                int col = bn + wn + g * 16 + h * 8 + qcol;
                float b0 = sbias[col - bn];
                float b1 = sbias[col - bn + 1];
                float* cc = c[mt][2 * g + h];
                *reinterpret_cast<float2*>(&out[(size_t)r0 * DOUT + col]) =
                    make_float2(cc[0] + b0, cc[1] + b1);
                *reinterpret_cast<float2*>(&out[(size_t)(r0 + 8) * DOUT + col]) =
                    make_float2(cc[2] + b0, cc[3] + b1);
            }
        }
    }
}

// ---------------------------------------------------------------------------
extern "C" void kernel_launch(void* const* d_in, const int* in_sizes, int n_in,
                              void* d_out, int out_size) {
    const float* x      = (const float*)d_in[0];
    const int*   qw     = (const int*)  d_in[1];
    const float* scales = (const float*)d_in[2];
    const float* bias   = (const float*)d_in[3];
    const float* lA     = (const float*)d_in[4];
    const float* lB     = (const float*)d_in[5];
    float*       out    = (float*)d_out;

    {
        dim3 grid(DIN / 64, DOUT / 64);
        prep_w_kernel<<<grid, 256>>>(qw, scales, lA, lB);
    }
    {
        size_t total = (size_t)MROWS * DIN / 8;
        prep_x_kernel<<<(int)((total + 255) / 256), 256>>>(x);
    }
    {
        cudaFuncSetAttribute(qlora_hmma_kernel,
                             cudaFuncAttributeMaxDynamicSharedMemorySize, SMEM_DYN);
        dim3 grid(DOUT / BN, MROWS / BM);
        qlora_hmma_kernel<<<grid, 256, SMEM_DYN>>>(bias, out);
    }
}

// round 11
// speedup vs baseline: 4.8615x; 1.4711x over previous
#include <cuda_runtime.h>
#include <cuda_fp16.h>
#include <cstdint>

#define DIN   4096
#define DOUT  4096
#define MROWS 8192
#define RANK  16

#define BM 128
#define BN 256
#define BK 32
#define STAGES 5
#define NCHUNK (DIN / BK)            // 128

// 80-byte row stride (40 halves): conflict-free ldmatrix.
#define ROWB 80
#define A_BYTES (BM * ROWB)          // 10240
#define B_BYTES (BN * ROWB)          // 20480
#define STAGE_BYTES (A_BYTES + B_BYTES)  // 30720
#define SMEM_DYN (STAGES * STAGE_BYTES + 2048)  // ~155 KB

__device__ __half g_Xh[(size_t)MROWS * DIN];   // 64 MB
__device__ __half g_Wh[(size_t)DOUT * DIN];    // 32 MB  W_eff[n][k]

// ---------------------------------------------------------------------------
// Prep 1: W_eff[n][k] = scale*Q[n][k] + (A@B)[k][n], fp16(rn).
// lA rows in registers; lB staged in smem transposed [n][r] for LDS.128.
// ---------------------------------------------------------------------------
__global__ __launch_bounds__(256)
void prep_w_kernel(const int*   __restrict__ qw,
                   const float* __restrict__ scales,
                   const float* __restrict__ lA,   // [DIN][RANK]
                   const float* __restrict__ lB) { // [RANK][DOUT]
    __shared__ __align__(16) float sB[64 * 20];    // [n][r], pad 20
    const int tid  = threadIdx.x;
    const int lane = tid & 31;
    const int w    = tid >> 5;
    const int k0   = blockIdx.x * 64 + lane * 2;
    const int nb0  = blockIdx.y * 64;

#pragma unroll
    for (int j = 0; j < 4; j++) {
        int idx = tid + j * 256;
        int r = idx >> 6, n = idx & 63;            // coalesced gmem read
        sB[n * 20 + r] = lB[(size_t)r * DOUT + nb0 + n];
    }

    float a[32];  // a[0..15] = lA[k0][:], a[16..31] = lA[k0+1][:]
    const float4* pa = reinterpret_cast<const float4*>(&lA[(size_t)k0 * RANK]);
#pragma unroll
    for (int q = 0; q < 8; q++)
        reinterpret_cast<float4*>(a)[q] = pa[q];

    __syncthreads();

    const float s = scales[0];
#pragma unroll
    for (int j = 0; j < 8; j++) {
        const int nl = w * 8 + j;
        const int n  = nb0 + nl;
        int2 q2 = *reinterpret_cast<const int2*>(&qw[(size_t)n * DIN + k0]);
        float acc0 = (float)q2.x * s;
        float acc1 = (float)q2.y * s;
        float bq[16];
#pragma unroll
        for (int q = 0; q < 4; q++)                // 4x LDS.128, broadcast
            reinterpret_cast<float4*>(bq)[q] =
                *reinterpret_cast<const float4*>(&sB[nl * 20 + q * 4]);
#pragma unroll
        for (int r = 0; r < RANK; r++) {
            acc0 += a[r]      * bq[r];
            acc1 += a[16 + r] * bq[r];
        }
        *reinterpret_cast<__half2*>(&g_Wh[(size_t)n * DIN + k0]) =
            __floats2half2_rn(acc0, acc1);
    }
}

// ---------------------------------------------------------------------------
__global__ void prep_x_kernel(const float* __restrict__ x) {
    size_t t = (size_t)blockIdx.x * blockDim.x + threadIdx.x;
    size_t base = t * 8;
    if (base >= (size_t)MROWS * DIN) return;
    float4 v0 = *reinterpret_cast<const float4*>(x + base);
    float4 v1 = *reinterpret_cast<const float4*>(x + base + 4);
    __half2 h[4];
    h[0] = __floats2half2_rn(v0.x, v0.y);
    h[1] = __floats2half2_rn(v0.z, v0.w);
    h[2] = __floats2half2_rn(v1.x, v1.y);
    h[3] = __floats2half2_rn(v1.z, v1.w);
    *reinterpret_cast<uint4*>(&g_Xh[base]) = *reinterpret_cast<uint4*>(h);
}

// ---------------------------------------------------------------------------
__device__ __forceinline__ uint32_t smem_u32(const void* p) {
    uint32_t a;
    asm("{ .reg .u64 t; cvta.to.shared.u64 t, %1; cvt.u32.u64 %0, t; }" : "=r"(a) : "l"(p));
    return a;
}
__device__ __forceinline__ void cp16(uint32_t dst, const void* src) {
    asm volatile("cp.async.cg.shared.global [%0], [%1], 16;" :: "r"(dst), "l"(src));
}
__device__ __forceinline__ void ldsm4(uint32_t& r0, uint32_t& r1, uint32_t& r2,
                                      uint32_t& r3, uint32_t addr) {
    asm volatile("ldmatrix.sync.aligned.m8n8.x4.shared.b16 {%0,%1,%2,%3}, [%4];"
                 : "=r"(r0), "=r"(r1), "=r"(r2), "=r"(r3) : "r"(addr));
}
__device__ __forceinline__ void mma16816(float* c, const uint32_t* a,
                                         const uint32_t* b) {
    asm volatile(
        "mma.sync.aligned.m16n8k16.row.col.f32.f16.f16.f32 "
        "{%0,%1,%2,%3}, {%4,%5,%6,%7}, {%8,%9}, {%0,%1,%2,%3};\n"
        : "+f"(c[0]), "+f"(c[1]), "+f"(c[2]), "+f"(c[3])
        : "r"(a[0]), "r"(a[1]), "r"(a[2]), "r"(a[3]), "r"(b[0]), "r"(b[1]));
}

// ---------------------------------------------------------------------------
// GEMM with register-double-buffered fragments: LDSM for step s+1 issued
// before MMAs of step s, across chunk boundaries, so the tensor pipe never
// waits on shared-memory latency or barrier phases.
// ---------------------------------------------------------------------------
__global__ __launch_bounds__(256)
void qlora_hmma_kernel(const float* __restrict__ bias,
                       float*       __restrict__ out) {
    extern __shared__ char smem_raw[];
    uint32_t sbase = smem_u32(smem_raw);
    float* sbias = (float*)(smem_raw + STAGES * STAGE_BYTES);

    const int tid  = threadIdx.x;
    const int warp = tid >> 5;
    const int lane = tid & 31;
    const int bm = blockIdx.y * BM;
    const int bn = blockIdx.x * BN;
    const int wm = (warp >> 2) * 64;
    const int wn = (warp & 3) * 64;

    sbias[tid] = bias[bn + tid];

    const uint32_t a_loff = (uint32_t)((lane & 15) * ROWB + (lane >> 4) * 16)
                            + (uint32_t)wm * ROWB;
    const uint32_t b_loff = (uint32_t)((((lane >> 4) << 3) + (lane & 7)) * ROWB
                                       + ((lane >> 3) & 1) * 16)
                            + (uint32_t)wn * ROWB + A_BYTES;

    float c[4][8][4];
#pragma unroll
    for (int i = 0; i < 4; i++)
#pragma unroll
        for (int j = 0; j < 8; j++)
#pragma unroll
            for (int q = 0; q < 4; q++) c[i][j][q] = 0.f;

    uint32_t a0[4][4], b0[4][4], a1[4][4], b1[4][4];

    auto load_chunk = [&](int chunk, int slot) {
        const int k0 = chunk * BK;
        uint32_t abase = sbase + slot * STAGE_BYTES;
        uint32_t bbase = abase + A_BYTES;
#pragma unroll
        for (int j = 0; j < 2; j++) {
            int id = tid + j * 256;
            int row = id >> 2, cc = id & 3;
            cp16(abase + row * ROWB + cc * 16,
                 &g_Xh[(size_t)(bm + row) * DIN + k0 + cc * 8]);
        }
#pragma unroll
        for (int j = 0; j < 4; j++) {
            int id = tid + j * 256;
            int row = id >> 2, cc = id & 3;
            cp16(bbase + row * ROWB + cc * 16,
                 &g_Wh[(size_t)(bn + row) * DIN + k0 + cc * 8]);
        }
    };
    auto ldsm_step = [&](uint32_t (&a)[4][4], uint32_t (&b)[4][4],
                         int slot, int s) {
        uint32_t ab = sbase + (uint32_t)slot * STAGE_BYTES + a_loff + (uint32_t)(s * 32);
        uint32_t bb = sbase + (uint32_t)slot * STAGE_BYTES + b_loff + (uint32_t)(s * 32);
#pragma unroll
        for (int mt = 0; mt < 4; mt++)
            ldsm4(a[mt][0], a[mt][1], a[mt][2], a[mt][3],
                  ab + (uint32_t)(mt * 16 * ROWB));
#pragma unroll
        for (int g = 0; g < 4; g++)
            ldsm4(b[g][0], b[g][1], b[g][2], b[g][3],
                  bb + (uint32_t)(g * 16 * ROWB));
    };
    auto mma_step = [&](uint32_t (&a)[4][4], uint32_t (&b)[4][4]) {
#pragma unroll
        for (int mt = 0; mt < 4; mt++)
#pragma unroll
            for (int g = 0; g < 4; g++) {
                mma16816(c[mt][2 * g],     a[mt], &b[g][0]);
                mma16816(c[mt][2 * g + 1], a[mt], &b[g][2]);
            }
    };

    // ---- prologue: fill 4 stages, land chunks 0..1, preload f0 ----
#pragma unroll
    for (int s = 0; s < STAGES - 1; s++) {
        load_chunk(s, s);
        asm volatile("cp.async.commit_group;" ::: "memory");
    }
    asm volatile("cp.async.wait_group 2;" ::: "memory");
    __syncthreads();
    ldsm_step(a0, b0, 0, 0);

    // ---- mainloop ----
    int slot_cur = 0, slot_nxt = 1, slot_cp = STAGES - 1;
    for (int i = 0; i < NCHUNK; i++) {
        ldsm_step(a1, b1, slot_cur, 1);      // frags (i, s1)
        mma_step(a0, b0);                    // compute (i, s0)

        asm volatile("cp.async.wait_group 2;" ::: "memory");
        __syncthreads();

        if (i + 1 < NCHUNK)
            ldsm_step(a0, b0, slot_nxt, 0);  // frags (i+1, s0)
        if (i + STAGES - 1 < NCHUNK)
            load_chunk(i + STAGES - 1, slot_cp);
        asm volatile("cp.async.commit_group;" ::: "memory");

        mma_step(a1, b1);                    // compute (i, s1)

        slot_cur = slot_nxt;
        slot_nxt = (slot_nxt == STAGES - 1) ? 0 : slot_nxt + 1;
        slot_cp  = (slot_cp  == STAGES - 1) ? 0 : slot_cp  + 1;
    }

    // ---- epilogue: + bias, fp32 stores ----
    const int qrow = lane >> 2;
    const int qcol = (lane & 3) * 2;
#pragma unroll
    for (int mt = 0; mt < 4; mt++) {
        int r0 = bm + wm + mt * 16 + qrow;
#pragma unroll
        for (int g = 0; g < 4; g++) {
#pragma unroll
            for (int h = 0; h < 2; h++) {
                int col = bn + wn + g * 16 + h * 8 + qcol;
                float bb0 = sbias[col - bn];
                float bb1 = sbias[col - bn + 1];
                float* cc = c[mt][2 * g + h];
                *reinterpret_cast<float2*>(&out[(size_t)r0 * DOUT + col]) =
                    make_float2(cc[0] + bb0, cc[1] + bb1);
                *reinterpret_cast<float2*>(&out[(size_t)(r0 + 8) * DOUT + col]) =
                    make_float2(cc[2] + bb0, cc[3] + bb1);
            }
        }
    }
}

// ---------------------------------------------------------------------------
extern "C" void kernel_launch(void* const* d_in, const int* in_sizes, int n_in,
                              void* d_out, int out_size) {
    const float* x      = (const float*)d_in[0];
    const int*   qw     = (const int*)  d_in[1];
    const float* scales = (const float*)d_in[2];
    const float* bias   = (const float*)d_in[3];
    const float* lA     = (const float*)d_in[4];
    const float* lB     = (const float*)d_in[5];
    float*       out    = (float*)d_out;

    {
        dim3 grid(DIN / 64, DOUT / 64);
        prep_w_kernel<<<grid, 256>>>(qw, scales, lA, lB);
    }
    {
        size_t total = (size_t)MROWS * DIN / 8;
        prep_x_kernel<<<(int)((total + 255) / 256), 256>>>(x);
    }
    {
        cudaFuncSetAttribute(qlora_hmma_kernel,
                             cudaFuncAttributeMaxDynamicSharedMemorySize, SMEM_DYN);
        dim3 grid(DOUT / BN, MROWS / BM);
        qlora_hmma_kernel<<<grid, 256, SMEM_DYN>>>(bias, out);
    }
}

// round 12
// speedup vs baseline: 5.0355x; 1.0358x over previous
#include <cuda_runtime.h>
#include <cuda_fp16.h>
#include <cstdint>

#define DIN   4096
#define DOUT  4096
#define MROWS 8192
#define RANK  16

#define BM 128
#define BN 256
#define BK 64
#define STAGES 3
#define NCHUNK (DIN / BK)            // 64

// 144-byte row stride (64 halves + 16B pad): conflict-free ldmatrix & cp.async
// (bank base 36*r mod 32 = 4r distinct over each 8-row phase).
#define ROWB 144
#define A_BYTES (BM * ROWB)          // 18432
#define B_BYTES (BN * ROWB)          // 36864
#define STAGE_BYTES (A_BYTES + B_BYTES)  // 55296
#define SMEM_DYN (STAGES * STAGE_BYTES + 2048)  // 167936

__device__ __half g_Xh[(size_t)MROWS * DIN];   // 64 MB
__device__ __half g_Wh[(size_t)DOUT * DIN];    // 32 MB  W_eff[n][k]

// ---------------------------------------------------------------------------
// Fused prep: blocks [0,4096) build W_eff (fp16), blocks [4096,20480) convert
// x -> fp16. Streaming X blocks overlap W blocks' tail.
// ---------------------------------------------------------------------------
#define W_BLOCKS 4096
#define X_BLOCKS ((MROWS * DIN) / (256 * 8))   // 16384

__global__ __launch_bounds__(256)
void prep_kernel(const int*   __restrict__ qw,
                 const float* __restrict__ scales,
                 const float* __restrict__ lA,   // [DIN][RANK]
                 const float* __restrict__ lB,   // [RANK][DOUT]
                 const float* __restrict__ x) {
    __shared__ __align__(16) float sB[64 * 20];
    const int bid = blockIdx.x;
    const int tid = threadIdx.x;

    if (bid < W_BLOCKS) {
        const int lane = tid & 31;
        const int w    = tid >> 5;
        const int k0   = (bid & 63) * 64 + lane * 2;
        const int nb0  = (bid >> 6) * 64;

#pragma unroll
        for (int j = 0; j < 4; j++) {
            int idx = tid + j * 256;
            int r = idx >> 6, n = idx & 63;
            sB[n * 20 + r] = lB[(size_t)r * DOUT + nb0 + n];
        }

        float a[32];
        const float4* pa = reinterpret_cast<const float4*>(&lA[(size_t)k0 * RANK]);
#pragma unroll
        for (int q = 0; q < 8; q++)
            reinterpret_cast<float4*>(a)[q] = pa[q];

        __syncthreads();

        const float s = scales[0];
#pragma unroll
        for (int j = 0; j < 8; j++) {
            const int nl = w * 8 + j;
            const int n  = nb0 + nl;
            int2 q2 = *reinterpret_cast<const int2*>(&qw[(size_t)n * DIN + k0]);
            float acc0 = (float)q2.x * s;
            float acc1 = (float)q2.y * s;
            float bq[16];
#pragma unroll
            for (int q = 0; q < 4; q++)
                reinterpret_cast<float4*>(bq)[q] =
                    *reinterpret_cast<const float4*>(&sB[nl * 20 + q * 4]);
#pragma unroll
            for (int r = 0; r < RANK; r++) {
                acc0 += a[r]      * bq[r];
                acc1 += a[16 + r] * bq[r];
            }
            *reinterpret_cast<__half2*>(&g_Wh[(size_t)n * DIN + k0]) =
                __floats2half2_rn(acc0, acc1);
        }
    } else {
        size_t base = ((size_t)(bid - W_BLOCKS) * 256 + tid) * 8;
        float4 v0 = *reinterpret_cast<const float4*>(x + base);
        float4 v1 = *reinterpret_cast<const float4*>(x + base + 4);
        __half2 h[4];
        h[0] = __floats2half2_rn(v0.x, v0.y);
        h[1] = __floats2half2_rn(v0.z, v0.w);
        h[2] = __floats2half2_rn(v1.x, v1.y);
        h[3] = __floats2half2_rn(v1.z, v1.w);
        *reinterpret_cast<uint4*>(&g_Xh[base]) = *reinterpret_cast<uint4*>(h);
    }
}

// ---------------------------------------------------------------------------
__device__ __forceinline__ uint32_t smem_u32(const void* p) {
    uint32_t a;
    asm("{ .reg .u64 t; cvta.to.shared.u64 t, %1; cvt.u32.u64 %0, t; }" : "=r"(a) : "l"(p));
    return a;
}
__device__ __forceinline__ void cp16(uint32_t dst, const void* src) {
    asm volatile("cp.async.cg.shared.global [%0], [%1], 16;" :: "r"(dst), "l"(src));
}
__device__ __forceinline__ void ldsm4(uint32_t& r0, uint32_t& r1, uint32_t& r2,
                                      uint32_t& r3, uint32_t addr) {
    asm volatile("ldmatrix.sync.aligned.m8n8.x4.shared.b16 {%0,%1,%2,%3}, [%4];"
                 : "=r"(r0), "=r"(r1), "=r"(r2), "=r"(r3) : "r"(addr));
}
__device__ __forceinline__ void mma16816(float* c, const uint32_t* a,
                                         const uint32_t* b) {
    asm volatile(
        "mma.sync.aligned.m16n8k16.row.col.f32.f16.f16.f32 "
        "{%0,%1,%2,%3}, {%4,%5,%6,%7}, {%8,%9}, {%0,%1,%2,%3};\n"
        : "+f"(c[0]), "+f"(c[1]), "+f"(c[2]), "+f"(c[3])
        : "r"(a[0]), "r"(a[1]), "r"(a[2]), "r"(a[3]), "r"(b[0]), "r"(b[1]));
}

// ---------------------------------------------------------------------------
// GEMM: BK=64 chunks (4 k16 steps), register double-buffered fragments,
// one wait_group+barrier per 64-K chunk (half the sync events of BK=32).
// ---------------------------------------------------------------------------
__global__ __launch_bounds__(256)
void qlora_hmma_kernel(const float* __restrict__ bias,
                       float*       __restrict__ out) {
    extern __shared__ char smem_raw[];
    uint32_t sbase = smem_u32(smem_raw);
    float* sbias = (float*)(smem_raw + STAGES * STAGE_BYTES);

    const int tid  = threadIdx.x;
    const int warp = tid >> 5;
    const int lane = tid & 31;
    const int bm = blockIdx.y * BM;
    const int bn = blockIdx.x * BN;
    const int wm = (warp >> 2) * 64;
    const int wn = (warp & 3) * 64;

    sbias[tid] = bias[bn + tid];

    const uint32_t a_loff = (uint32_t)((lane & 15) * ROWB + (lane >> 4) * 16)
                            + (uint32_t)wm * ROWB;
    const uint32_t b_loff = (uint32_t)((((lane >> 4) << 3) + (lane & 7)) * ROWB
                                       + ((lane >> 3) & 1) * 16)
                            + (uint32_t)wn * ROWB + A_BYTES;

    float c[4][8][4];
#pragma unroll
    for (int i = 0; i < 4; i++)
#pragma unroll
        for (int j = 0; j < 8; j++)
#pragma unroll
            for (int q = 0; q < 4; q++) c[i][j][q] = 0.f;

    uint32_t a0[4][4], b0[4][4], a1[4][4], b1[4][4];

    auto load_chunk = [&](int chunk, int slot) {
        const int k0 = chunk * BK;
        uint32_t abase = sbase + slot * STAGE_BYTES;
        uint32_t bbase = abase + A_BYTES;
#pragma unroll
        for (int j = 0; j < 4; j++) {               // A: 1024 x 16B
            int id = tid + j * 256;
            int row = id >> 3, cc = id & 7;
            cp16(abase + row * ROWB + cc * 16,
                 &g_Xh[(size_t)(bm + row) * DIN + k0 + cc * 8]);
        }
#pragma unroll
        for (int j = 0; j < 8; j++) {               // B: 2048 x 16B
            int id = tid + j * 256;
            int row = id >> 3, cc = id & 7;
            cp16(bbase + row * ROWB + cc * 16,
                 &g_Wh[(size_t)(bn + row) * DIN + k0 + cc * 8]);
        }
    };
    auto ldsm_step = [&](uint32_t (&a)[4][4], uint32_t (&b)[4][4],
                         int slot, int s) {
        uint32_t ab = sbase + (uint32_t)slot * STAGE_BYTES + a_loff + (uint32_t)(s * 32);
        uint32_t bb = sbase + (uint32_t)slot * STAGE_BYTES + b_loff + (uint32_t)(s * 32);
#pragma unroll
        for (int mt = 0; mt < 4; mt++)
            ldsm4(a[mt][0], a[mt][1], a[mt][2], a[mt][3],
                  ab + (uint32_t)(mt * 16 * ROWB));
#pragma unroll
        for (int g = 0; g < 4; g++)
            ldsm4(b[g][0], b[g][1], b[g][2], b[g][3],
                  bb + (uint32_t)(g * 16 * ROWB));
    };
    auto mma_step = [&](uint32_t (&a)[4][4], uint32_t (&b)[4][4]) {
#pragma unroll
        for (int mt = 0; mt < 4; mt++)
#pragma unroll
            for (int g = 0; g < 4; g++) {
                mma16816(c[mt][2 * g],     a[mt], &b[g][0]);
                mma16816(c[mt][2 * g + 1], a[mt], &b[g][2]);
            }
    };

    // ---- prologue: fill 3 stages, land chunks 0..1, preload f0=(0,s0) ----
#pragma unroll
    for (int s = 0; s < STAGES; s++) {
        load_chunk(s, s);
        asm volatile("cp.async.commit_group;" ::: "memory");
    }
    asm volatile("cp.async.wait_group 1;" ::: "memory");
    __syncthreads();
    ldsm_step(a0, b0, 0, 0);

    // ---- mainloop: 64 iterations, one barrier each ----
    int slot_cur = 0, slot_nxt = 1;
    for (int i = 0; i < NCHUNK; i++) {
        ldsm_step(a1, b1, slot_cur, 1); mma_step(a0, b0);   // (i,s0)
        ldsm_step(a0, b0, slot_cur, 2); mma_step(a1, b1);   // (i,s1)
        ldsm_step(a1, b1, slot_cur, 3); mma_step(a0, b0);   // (i,s2)

        asm volatile("cp.async.wait_group 1;" ::: "memory"); // chunk i+1 landed
        __syncthreads();                                     // all reads of chunk i done

        if (i + 1 < NCHUNK)
            ldsm_step(a0, b0, slot_nxt, 0);                  // (i+1,s0)
        if (i + STAGES < NCHUNK)
            load_chunk(i + STAGES, slot_cur);                // slot(i+3) == slot(i)
        asm volatile("cp.async.commit_group;" ::: "memory");

        mma_step(a1, b1);                                    // (i,s3)

        slot_cur = slot_nxt;
        slot_nxt = (slot_nxt == STAGES - 1) ? 0 : slot_nxt + 1;
    }

    // ---- epilogue: + bias, fp32 stores ----
    const int qrow = lane >> 2;
    const int qcol = (lane & 3) * 2;
#pragma unroll
    for (int mt = 0; mt < 4; mt++) {
        int r0 = bm + wm + mt * 16 + qrow;
#pragma unroll
        for (int g = 0; g < 4; g++) {
#pragma unroll
            for (int h = 0; h < 2; h++) {
                int col = bn + wn + g * 16 + h * 8 + qcol;
                float bb0 = sbias[col - bn];
                float bb1 = sbias[col - bn + 1];
                float* cc = c[mt][2 * g + h];
                *reinterpret_cast<float2*>(&out[(size_t)r0 * DOUT + col]) =
                    make_float2(cc[0] + bb0, cc[1] + bb1);
                *reinterpret_cast<float2*>(&out[(size_t)(r0 + 8) * DOUT + col]) =
                    make_float2(cc[2] + bb0, cc[3] + bb1);
            }
        }
    }
}

// ---------------------------------------------------------------------------
extern "C" void kernel_launch(void* const* d_in, const int* in_sizes, int n_in,
                              void* d_out, int out_size) {
    const float* x      = (const float*)d_in[0];
    const int*   qw     = (const int*)  d_in[1];
    const float* scales = (const float*)d_in[2];
    const float* bias   = (const float*)d_in[3];
    const float* lA     = (const float*)d_in[4];
    const float* lB     = (const float*)d_in[5];
    float*       out    = (float*)d_out;

    prep_kernel<<<W_BLOCKS + X_BLOCKS, 256>>>(qw, scales, lA, lB, x);
    {
        cudaFuncSetAttribute(qlora_hmma_kernel,
                             cudaFuncAttributeMaxDynamicSharedMemorySize, SMEM_DYN);
        dim3 grid(DOUT / BN, MROWS / BM);
        qlora_hmma_kernel<<<grid, 256, SMEM_DYN>>>(bias, out);
    }
}